// round 1
// baseline (speedup 1.0000x reference)
#include <cuda_runtime.h>

#define SS 1024
#define DD 512
#define HH 8
#define DKK 64
#define BBB 8
#define NQ (BBB*SS)   // 8192

// Scratch (allocation-free requirement -> __device__ globals)
__device__ float g_Q[NQ*DD];
__device__ float g_K[NQ*DD];
__device__ float g_V[NQ*DD];
__device__ float g_X[NQ*DD];

// ---------------------------------------------------------------------------
// C[M,N] = A[M,K] @ W[N,K]^T (+ bias[N])   -- 64x64 tile, BK=16, 256 threads
// ---------------------------------------------------------------------------
__global__ __launch_bounds__(256) void gemm_xwT(
    const float* __restrict__ A, const float* __restrict__ W,
    const float* __restrict__ bias, float* __restrict__ C,
    int M, int N, int Kd)
{
    __shared__ float As[64][17];
    __shared__ float Ws[64][17];
    const int tid = threadIdx.x;
    const int tx = tid & 15, ty = tid >> 4;
    const int row0 = blockIdx.y * 64, col0 = blockIdx.x * 64;
    float acc[4][4] = {};

    for (int k0 = 0; k0 < Kd; k0 += 16) {
        #pragma unroll
        for (int u = 0; u < 4; ++u) {
            int idx = tid + 256*u;          // 0..1023
            int r = idx >> 4, kk = idx & 15;
            As[r][kk] = A[(row0 + r)*Kd + k0 + kk];
            Ws[r][kk] = W[(col0 + r)*Kd + k0 + kk];
        }
        __syncthreads();
        #pragma unroll
        for (int kk = 0; kk < 16; ++kk) {
            float a[4], bv[4];
            #pragma unroll
            for (int i = 0; i < 4; ++i) a[i]  = As[ty*4+i][kk];
            #pragma unroll
            for (int j = 0; j < 4; ++j) bv[j] = Ws[tx*4+j][kk];
            #pragma unroll
            for (int i = 0; i < 4; ++i)
                #pragma unroll
                for (int j = 0; j < 4; ++j)
                    acc[i][j] = fmaf(a[i], bv[j], acc[i][j]);
        }
        __syncthreads();
    }
    #pragma unroll
    for (int i = 0; i < 4; ++i) {
        int r = row0 + ty*4 + i;
        #pragma unroll
        for (int j = 0; j < 4; ++j) {
            int c = col0 + tx*4 + j;
            float v = acc[i][j];
            if (bias) v += bias[c];
            C[r*N + c] = v;
        }
    }
}

// ---------------------------------------------------------------------------
// Flash-style attention with post-softmax group_prob scaling.
// grid = (H, S/64, B), block = 256.  CTA handles one (b,h,qtile of 64).
// Online softmax: m (running max), l (sum exp WITHOUT g), acc (sum exp*g*v).
// Masked entries -> prob exactly 0 (matches fp32 underflow of exp(-1e9-m)).
// ---------------------------------------------------------------------------
// Dynamic smem layout (floats):
//  Qs   [64*64]   q-major  [q][d]
//  KVs  [64*65]   K phase: d-major Kt[d][k] ; V phase: k-major V[k][d]
//  Ps   [64*65]   [q][k] scores -> probs
//  m_s, l_s, al_s [64] each
#define QS_OFF   0
#define KV_OFF   (64*64)
#define PS_OFF   (KV_OFF + 64*65)
#define M_OFF    (PS_OFF + 64*65)
#define L_OFF    (M_OFF + 64)
#define AL_OFF   (L_OFF + 64)
#define SMEM_FLOATS (AL_OFF + 64)
#define SMEM_BYTES  (SMEM_FLOATS * 4)

__global__ __launch_bounds__(256) void attn_kernel(
    const float* __restrict__ Q, const float* __restrict__ K,
    const float* __restrict__ V, const float* __restrict__ gprob,
    const int* __restrict__ mask, float* __restrict__ X)
{
    extern __shared__ float sm[];
    float* Qs  = sm + QS_OFF;
    float* KVs = sm + KV_OFF;
    float* Ps  = sm + PS_OFF;
    float* m_s = sm + M_OFF;
    float* l_s = sm + L_OFF;
    float* al_s= sm + AL_OFF;

    const int h  = blockIdx.x;
    const int qt = blockIdx.y;
    const int b  = blockIdx.z;
    const int tid = threadIdx.x;
    const int tx = tid & 15, ty = tid >> 4;
    const int q0 = qt * 64;

    const float* Qbase = Q + (b*SS)*DD + h*DKK;
    const float* Kbase = K + (b*SS)*DD + h*DKK;
    const float* Vbase = V + (b*SS)*DD + h*DKK;
    const int mbase = (b*SS)*SS;              // (b*S + q)*S + k, max 8.4M

    // Load Q tile [q][d]
    #pragma unroll
    for (int u = 0; u < 16; ++u) {
        int idx = tid + 256*u;                // 0..4095
        int q = idx >> 6, d = idx & 63;
        Qs[q*64 + d] = Qbase[(q0 + q)*DD + d];
    }
    if (tid < 64) { m_s[tid] = -3.0e38f; l_s[tid] = 0.0f; }
    float acc[4][4] = {};
    __syncthreads();

    for (int kt = 0; kt < 16; ++kt) {
        const int k0 = kt * 64;

        // Load K transposed: Kt[d][k], stride 65 (conflict-free store)
        #pragma unroll
        for (int u = 0; u < 16; ++u) {
            int idx = tid + 256*u;
            int k = idx >> 6, d = idx & 63;
            KVs[d*65 + k] = Kbase[(k0 + k)*DD + d];
        }
        __syncthreads();

        // Scores: s[q][k] = (Q . K) / 8, masked -> -3e38
        float s[4][4] = {};
        #pragma unroll
        for (int dd = 0; dd < 64; ++dd) {
            float a[4], bv[4];
            #pragma unroll
            for (int i = 0; i < 4; ++i) a[i]  = Qs[(ty*4+i)*64 + dd];
            #pragma unroll
            for (int j = 0; j < 4; ++j) bv[j] = KVs[dd*65 + tx*4 + j];
            #pragma unroll
            for (int i = 0; i < 4; ++i)
                #pragma unroll
                for (int j = 0; j < 4; ++j)
                    s[i][j] = fmaf(a[i], bv[j], s[i][j]);
        }
        #pragma unroll
        for (int i = 0; i < 4; ++i) {
            int qg = q0 + ty*4 + i;
            #pragma unroll
            for (int j = 0; j < 4; ++j) {
                int kg = k0 + tx*4 + j;
                int mm = mask[mbase + qg*SS + kg];
                float sv = s[i][j] * 0.125f;
                if (!(mm || (qg == kg))) sv = -3.0e38f;
                Ps[(ty*4+i)*65 + tx*4 + j] = sv;
            }
        }
        __syncthreads();

        // Row max + alpha (64 row-threads; pad-65 -> conflict-free)
        if (tid < 64) {
            float mold = m_s[tid];
            float r = mold;
            #pragma unroll 8
            for (int kk = 0; kk < 64; ++kk) r = fmaxf(r, Ps[tid*65 + kk]);
            m_s[tid]  = r;
            al_s[tid] = __expf(mold - r);   // (-3e38)-(-3e38)=0 -> 1, safe
        }
        __syncthreads();

        // exp(s - m); masked -> exactly 0
        #pragma unroll
        for (int i = 0; i < 4; ++i) {
            int q = ty*4 + i;
            float mnew = m_s[q];
            #pragma unroll
            for (int j = 0; j < 4; ++j) {
                float sv = Ps[q*65 + tx*4 + j];
                float p = (sv < -1.0e37f) ? 0.0f : __expf(sv - mnew);
                Ps[q*65 + tx*4 + j] = p;
            }
        }
        __syncthreads();

        // Row sum -> l update (BEFORE multiplying by group_prob)
        if (tid < 64) {
            float r = 0.0f;
            #pragma unroll 8
            for (int kk = 0; kk < 64; ++kk) r += Ps[tid*65 + kk];
            l_s[tid] = l_s[tid] * al_s[tid] + r;
        }
        __syncthreads();

        // p *= group_prob ; rescale acc ; load V tile [k][d]
        #pragma unroll
        for (int i = 0; i < 4; ++i) {
            int qg = q0 + ty*4 + i;
            #pragma unroll
            for (int j = 0; j < 4; ++j) {
                int kg = k0 + tx*4 + j;
                Ps[(ty*4+i)*65 + tx*4 + j] *= gprob[mbase + qg*SS + kg];
            }
        }
        #pragma unroll
        for (int i = 0; i < 4; ++i) {
            float al = al_s[ty*4 + i];
            #pragma unroll
            for (int j = 0; j < 4; ++j) acc[i][j] *= al;
        }
        #pragma unroll
        for (int u = 0; u < 16; ++u) {
            int idx = tid + 256*u;
            int k = idx >> 6, d = idx & 63;
            KVs[k*65 + d] = Vbase[(k0 + k)*DD + d];
        }
        __syncthreads();

        // acc += P @ V
        #pragma unroll 4
        for (int kk = 0; kk < 64; ++kk) {
            float a[4], bv[4];
            #pragma unroll
            for (int i = 0; i < 4; ++i) a[i]  = Ps[(ty*4+i)*65 + kk];
            #pragma unroll
            for (int j = 0; j < 4; ++j) bv[j] = KVs[kk*65 + tx*4 + j];
            #pragma unroll
            for (int i = 0; i < 4; ++i)
                #pragma unroll
                for (int j = 0; j < 4; ++j)
                    acc[i][j] = fmaf(a[i], bv[j], acc[i][j]);
        }
        __syncthreads();
    }

    // Write x[b, q, h*64+d] = acc / l
    float* Xbase = X + (b*SS + q0)*DD + h*DKK;
    #pragma unroll
    for (int i = 0; i < 4; ++i) {
        int q = ty*4 + i;
        float inv_l = 1.0f / l_s[q];
        #pragma unroll
        for (int j = 0; j < 4; ++j)
            Xbase[q*DD + tx*4 + j] = acc[i][j] * inv_l;
    }
}

// ---------------------------------------------------------------------------
extern "C" void kernel_launch(void* const* d_in, const int* in_sizes, int n_in,
                              void* d_out, int out_size)
{
    const float* query = (const float*)d_in[0];
    const float* key   = (const float*)d_in[1];
    const float* value = (const float*)d_in[2];
    const float* gprob = (const float*)d_in[3];
    const float* Wq    = (const float*)d_in[4];
    const float* Wk    = (const float*)d_in[5];
    const float* Wv    = (const float*)d_in[6];
    const float* Wh    = (const float*)d_in[7];
    const float* bh    = (const float*)d_in[8];
    const int*   mask  = (const int*)d_in[9];
    float* out = (float*)d_out;

    float *Qp, *Kp, *Vp, *Xp;
    cudaGetSymbolAddress((void**)&Qp, g_Q);
    cudaGetSymbolAddress((void**)&Kp, g_K);
    cudaGetSymbolAddress((void**)&Vp, g_V);
    cudaGetSymbolAddress((void**)&Xp, g_X);

    cudaFuncSetAttribute(attn_kernel,
                         cudaFuncAttributeMaxDynamicSharedMemorySize, SMEM_BYTES);

    dim3 blk(256);
    dim3 pg(DD/64, NQ/64);     // (8, 128)

    gemm_xwT<<<pg, blk>>>(query, Wq, nullptr, Qp, NQ, DD, DD);
    gemm_xwT<<<pg, blk>>>(key,   Wk, nullptr, Kp, NQ, DD, DD);
    gemm_xwT<<<pg, blk>>>(value, Wv, nullptr, Vp, NQ, DD, DD);

    // h fastest in grid.x -> 8 heads sharing mask/gprob rows run adjacently (L2 reuse)
    attn_kernel<<<dim3(HH, SS/64, BBB), blk, SMEM_BYTES>>>(Qp, Kp, Vp, gprob, mask, Xp);

    gemm_xwT<<<pg, blk>>>(Xp, Wh, bh, out, NQ, DD, DD);
}

// round 2
// speedup vs baseline: 1.0014x; 1.0014x over previous
#include <cuda_runtime.h>

#define SS 1024
#define DD 512
#define HH 8
#define DKK 64
#define BBB 8
#define NQ (BBB*SS)   // 8192

// Scratch (allocation-free requirement -> __device__ globals)
__device__ float g_Q[NQ*DD];
__device__ float g_K[NQ*DD];
__device__ float g_V[NQ*DD];
__device__ float g_X[NQ*DD];

// ---------------------------------------------------------------------------
// C[M,N] = A[M,K] @ W[N,K]^T (+ bias[N])   -- 64x64 tile, BK=16, 256 threads
// ---------------------------------------------------------------------------
__global__ __launch_bounds__(256) void gemm_xwT(
    const float* __restrict__ A, const float* __restrict__ W,
    const float* __restrict__ bias, float* __restrict__ C,
    int M, int N, int Kd)
{
    __shared__ float As[64][17];
    __shared__ float Ws[64][17];
    const int tid = threadIdx.x;
    const int tx = tid & 15, ty = tid >> 4;
    const int row0 = blockIdx.y * 64, col0 = blockIdx.x * 64;
    float acc[4][4] = {};

    for (int k0 = 0; k0 < Kd; k0 += 16) {
        #pragma unroll
        for (int u = 0; u < 4; ++u) {
            int idx = tid + 256*u;          // 0..1023
            int r = idx >> 4, kk = idx & 15;
            As[r][kk] = A[(row0 + r)*Kd + k0 + kk];
            Ws[r][kk] = W[(col0 + r)*Kd + k0 + kk];
        }
        __syncthreads();
        #pragma unroll
        for (int kk = 0; kk < 16; ++kk) {
            float a[4], bv[4];
            #pragma unroll
            for (int i = 0; i < 4; ++i) a[i]  = As[ty*4+i][kk];
            #pragma unroll
            for (int j = 0; j < 4; ++j) bv[j] = Ws[tx*4+j][kk];
            #pragma unroll
            for (int i = 0; i < 4; ++i)
                #pragma unroll
                for (int j = 0; j < 4; ++j)
                    acc[i][j] = fmaf(a[i], bv[j], acc[i][j]);
        }
        __syncthreads();
    }
    #pragma unroll
    for (int i = 0; i < 4; ++i) {
        int r = row0 + ty*4 + i;
        #pragma unroll
        for (int j = 0; j < 4; ++j) {
            int c = col0 + tx*4 + j;
            float v = acc[i][j];
            if (bias) v += bias[c];
            C[r*N + c] = v;
        }
    }
}

// ---------------------------------------------------------------------------
// Flash-style attention with post-softmax group_prob scaling.
// grid = (H, S/64, B), block = 256.  CTA handles one (b,h,qtile of 64).
// Online softmax: m (running max), l (sum exp WITHOUT g), acc (sum exp*g*v).
// Masked entries -> prob exactly 0 (matches fp32 underflow of exp(-1e9-m)).
// ---------------------------------------------------------------------------
// Dynamic smem layout (floats):
//  Qs   [64*64]   q-major  [q][d]
//  KVs  [64*65]   K phase: d-major Kt[d][k] ; V phase: k-major V[k][d]
//  Ps   [64*65]   [q][k] scores -> probs
//  m_s, l_s, al_s [64] each
#define QS_OFF   0
#define KV_OFF   (64*64)
#define PS_OFF   (KV_OFF + 64*65)
#define M_OFF    (PS_OFF + 64*65)
#define L_OFF    (M_OFF + 64)
#define AL_OFF   (L_OFF + 64)
#define SMEM_FLOATS (AL_OFF + 64)
#define SMEM_BYTES  (SMEM_FLOATS * 4)

__global__ __launch_bounds__(256) void attn_kernel(
    const float* __restrict__ Q, const float* __restrict__ K,
    const float* __restrict__ V, const float* __restrict__ gprob,
    const int* __restrict__ mask, float* __restrict__ X)
{
    extern __shared__ float sm[];
    float* Qs  = sm + QS_OFF;
    float* KVs = sm + KV_OFF;
    float* Ps  = sm + PS_OFF;
    float* m_s = sm + M_OFF;
    float* l_s = sm + L_OFF;
    float* al_s= sm + AL_OFF;

    const int h  = blockIdx.x;
    const int qt = blockIdx.y;
    const int b  = blockIdx.z;
    const int tid = threadIdx.x;
    const int tx = tid & 15, ty = tid >> 4;
    const int q0 = qt * 64;

    const float* Qbase = Q + (b*SS)*DD + h*DKK;
    const float* Kbase = K + (b*SS)*DD + h*DKK;
    const float* Vbase = V + (b*SS)*DD + h*DKK;
    const int mbase = (b*SS)*SS;              // (b*S + q)*S + k, max 8.4M

    // Load Q tile [q][d]
    #pragma unroll
    for (int u = 0; u < 16; ++u) {
        int idx = tid + 256*u;                // 0..4095
        int q = idx >> 6, d = idx & 63;
        Qs[q*64 + d] = Qbase[(q0 + q)*DD + d];
    }
    if (tid < 64) { m_s[tid] = -3.0e38f; l_s[tid] = 0.0f; }
    float acc[4][4] = {};
    __syncthreads();

    for (int kt = 0; kt < 16; ++kt) {
        const int k0 = kt * 64;

        // Load K transposed: Kt[d][k], stride 65 (conflict-free store)
        #pragma unroll
        for (int u = 0; u < 16; ++u) {
            int idx = tid + 256*u;
            int k = idx >> 6, d = idx & 63;
            KVs[d*65 + k] = Kbase[(k0 + k)*DD + d];
        }
        __syncthreads();

        // Scores: s[q][k] = (Q . K) / 8, masked -> -3e38
        float s[4][4] = {};
        #pragma unroll
        for (int dd = 0; dd < 64; ++dd) {
            float a[4], bv[4];
            #pragma unroll
            for (int i = 0; i < 4; ++i) a[i]  = Qs[(ty*4+i)*64 + dd];
            #pragma unroll
            for (int j = 0; j < 4; ++j) bv[j] = KVs[dd*65 + tx*4 + j];
            #pragma unroll
            for (int i = 0; i < 4; ++i)
                #pragma unroll
                for (int j = 0; j < 4; ++j)
                    s[i][j] = fmaf(a[i], bv[j], s[i][j]);
        }
        #pragma unroll
        for (int i = 0; i < 4; ++i) {
            int qg = q0 + ty*4 + i;
            #pragma unroll
            for (int j = 0; j < 4; ++j) {
                int kg = k0 + tx*4 + j;
                int mm = mask[mbase + qg*SS + kg];
                float sv = s[i][j] * 0.125f;
                if (!(mm || (qg == kg))) sv = -3.0e38f;
                Ps[(ty*4+i)*65 + tx*4 + j] = sv;
            }
        }
        __syncthreads();

        // Row max + alpha (64 row-threads; pad-65 -> conflict-free)
        if (tid < 64) {
            float mold = m_s[tid];
            float r = mold;
            #pragma unroll 8
            for (int kk = 0; kk < 64; ++kk) r = fmaxf(r, Ps[tid*65 + kk]);
            m_s[tid]  = r;
            al_s[tid] = __expf(mold - r);   // (-3e38)-(-3e38)=0 -> 1, safe
        }
        __syncthreads();

        // exp(s - m); masked -> exactly 0
        #pragma unroll
        for (int i = 0; i < 4; ++i) {
            int q = ty*4 + i;
            float mnew = m_s[q];
            #pragma unroll
            for (int j = 0; j < 4; ++j) {
                float sv = Ps[q*65 + tx*4 + j];
                float p = (sv < -1.0e37f) ? 0.0f : __expf(sv - mnew);
                Ps[q*65 + tx*4 + j] = p;
            }
        }
        __syncthreads();

        // Row sum -> l update (BEFORE multiplying by group_prob)
        if (tid < 64) {
            float r = 0.0f;
            #pragma unroll 8
            for (int kk = 0; kk < 64; ++kk) r += Ps[tid*65 + kk];
            l_s[tid] = l_s[tid] * al_s[tid] + r;
        }
        __syncthreads();

        // p *= group_prob ; rescale acc ; load V tile [k][d]
        #pragma unroll
        for (int i = 0; i < 4; ++i) {
            int qg = q0 + ty*4 + i;
            #pragma unroll
            for (int j = 0; j < 4; ++j) {
                int kg = k0 + tx*4 + j;
                Ps[(ty*4+i)*65 + tx*4 + j] *= gprob[mbase + qg*SS + kg];
            }
        }
        #pragma unroll
        for (int i = 0; i < 4; ++i) {
            float al = al_s[ty*4 + i];
            #pragma unroll
            for (int j = 0; j < 4; ++j) acc[i][j] *= al;
        }
        #pragma unroll
        for (int u = 0; u < 16; ++u) {
            int idx = tid + 256*u;
            int k = idx >> 6, d = idx & 63;
            KVs[k*65 + d] = Vbase[(k0 + k)*DD + d];
        }
        __syncthreads();

        // acc += P @ V
        #pragma unroll 4
        for (int kk = 0; kk < 64; ++kk) {
            float a[4], bv[4];
            #pragma unroll
            for (int i = 0; i < 4; ++i) a[i]  = Ps[(ty*4+i)*65 + kk];
            #pragma unroll
            for (int j = 0; j < 4; ++j) bv[j] = KVs[kk*65 + tx*4 + j];
            #pragma unroll
            for (int i = 0; i < 4; ++i)
                #pragma unroll
                for (int j = 0; j < 4; ++j)
                    acc[i][j] = fmaf(a[i], bv[j], acc[i][j]);
        }
        __syncthreads();
    }

    // Write x[b, q, h*64+d] = acc / l
    float* Xbase = X + (b*SS + q0)*DD + h*DKK;
    #pragma unroll
    for (int i = 0; i < 4; ++i) {
        int q = ty*4 + i;
        float inv_l = 1.0f / l_s[q];
        #pragma unroll
        for (int j = 0; j < 4; ++j)
            Xbase[q*DD + tx*4 + j] = acc[i][j] * inv_l;
    }
}

// ---------------------------------------------------------------------------
extern "C" void kernel_launch(void* const* d_in, const int* in_sizes, int n_in,
                              void* d_out, int out_size)
{
    const float* query = (const float*)d_in[0];
    const float* key   = (const float*)d_in[1];
    const float* value = (const float*)d_in[2];
    const float* gprob = (const float*)d_in[3];
    const float* Wq    = (const float*)d_in[4];
    const float* Wk    = (const float*)d_in[5];
    const float* Wv    = (const float*)d_in[6];
    const float* Wh    = (const float*)d_in[7];
    const float* bh    = (const float*)d_in[8];
    const int*   mask  = (const int*)d_in[9];
    float* out = (float*)d_out;

    float *Qp, *Kp, *Vp, *Xp;
    cudaGetSymbolAddress((void**)&Qp, g_Q);
    cudaGetSymbolAddress((void**)&Kp, g_K);
    cudaGetSymbolAddress((void**)&Vp, g_V);
    cudaGetSymbolAddress((void**)&Xp, g_X);

    cudaFuncSetAttribute(attn_kernel,
                         cudaFuncAttributeMaxDynamicSharedMemorySize, SMEM_BYTES);

    dim3 blk(256);
    dim3 pg(DD/64, NQ/64);     // (8, 128)

    gemm_xwT<<<pg, blk>>>(query, Wq, nullptr, Qp, NQ, DD, DD);
    gemm_xwT<<<pg, blk>>>(key,   Wk, nullptr, Kp, NQ, DD, DD);
    gemm_xwT<<<pg, blk>>>(value, Wv, nullptr, Vp, NQ, DD, DD);

    // h fastest in grid.x -> 8 heads sharing mask/gprob rows run adjacently (L2 reuse)
    attn_kernel<<<dim3(HH, SS/64, BBB), blk, SMEM_BYTES>>>(Qp, Kp, Vp, gprob, mask, Xp);

    gemm_xwT<<<pg, blk>>>(Xp, Wh, bh, out, NQ, DD, DD);
}

// round 6
// speedup vs baseline: 2.6587x; 2.6549x over previous
#include <cuda_runtime.h>
#include <cuda_bf16.h>

#define SS 1024
#define DD 512
#define HH 8
#define BBB 8
#define NQ (BBB*SS)
#define GP  72        // smem tile pitch in bf16 halves (padding -> conflict-free frags)
#define GPB 144       // pitch in bytes

__device__ float g_Q[NQ*DD];
__device__ float g_K[NQ*DD];
__device__ float g_V[NQ*DD];
__device__ float g_X[NQ*DD];

// ---------------------------------------------------------------------------
// helpers
// ---------------------------------------------------------------------------
__device__ __forceinline__ unsigned pack2bf(float x0, float x1) {
    unsigned r;
    asm("cvt.rn.bf16x2.f32 %0, %1, %2;" : "=r"(r) : "f"(x1), "f"(x0)); // low16=bf16(x0)
    return r;
}
// d += A(16x16) * B(16x8), bf16 inputs, f32 accum. Baseline sm_80+ ISA.
__device__ __forceinline__ void mma_bf16(float c[4], unsigned a0, unsigned a1,
                                         unsigned a2, unsigned a3,
                                         unsigned b0, unsigned b1) {
    asm volatile("mma.sync.aligned.m16n8k16.row.col.f32.bf16.bf16.f32 "
        "{%0,%1,%2,%3}, {%4,%5,%6,%7}, {%8,%9}, {%0,%1,%2,%3};"
        : "+f"(c[0]), "+f"(c[1]), "+f"(c[2]), "+f"(c[3])
        : "r"(a0), "r"(a1), "r"(a2), "r"(a3), "r"(b0), "r"(b1));
}
// split float4 into bf16 hi/lo and store 8B each at [r][cbyte] (pitch GPB)
__device__ __forceinline__ void sts_hilo(char* hib, char* lob, int r, int cbyte, float4 v) {
    unsigned hp0 = pack2bf(v.x, v.y), hp1 = pack2bf(v.z, v.w);
    float a0 = __uint_as_float(hp0 << 16), a1 = __uint_as_float(hp0 & 0xFFFF0000u);
    float a2 = __uint_as_float(hp1 << 16), a3 = __uint_as_float(hp1 & 0xFFFF0000u);
    unsigned lp0 = pack2bf(v.x - a0, v.y - a1), lp1 = pack2bf(v.z - a2, v.w - a3);
    *(uint2*)(hib + r*GPB + cbyte) = make_uint2(hp0, hp1);
    *(uint2*)(lob + r*GPB + cbyte) = make_uint2(lp0, lp1);
}
// single-element hi/lo split store at half-offset `hoff` (for V transpose)
__device__ __forceinline__ void split1(char* hib, char* lob, int hoff, float x) {
    __nv_bfloat16 hb = __float2bfloat16(x);
    __nv_bfloat16 lb = __float2bfloat16(x - __bfloat162float(hb));
    *(__nv_bfloat16*)(hib + hoff*2) = hb;
    *(__nv_bfloat16*)(lob + hoff*2) = lb;
}
__device__ __forceinline__ unsigned ldh2(const char* base, int hoff) {
    return *(const unsigned*)(base + hoff*2);   // hoff always even -> 4B aligned
}

// ===========================================================================
// GEMM: C[8192,512] = A[8192,512] @ W[512,512]^T (+bias)
// CTA 128x64, 8 warps in 4(M)x2(N), warp tile 32x32, k-chunks of 64.
// ===========================================================================
#define G_AH 0
#define G_AL 18432
#define G_WH 36864
#define G_WL 46080
#define G_SM 55296

__global__ __launch_bounds__(256) void gemm_mma(
    const float* __restrict__ A, const float* __restrict__ W,
    const float* __restrict__ bias, float* __restrict__ C)
{
    extern __shared__ char sm[];
    char* AH = sm + G_AH; char* AL = sm + G_AL;
    char* WH = sm + G_WH; char* WL = sm + G_WL;
    const int tid = threadIdx.x, lane = tid & 31, wid = tid >> 5;
    const int wm = wid & 3, wn = wid >> 2;
    const int g = lane >> 2, cq = lane & 3;
    const int m0 = blockIdx.y * 128, n0 = blockIdx.x * 64;

    float acc[2][4][4] = {};   // [mt][nt][frag]

    for (int kc = 0; kc < 8; ++kc) {
        const int k0 = kc * 64;
        #pragma unroll
        for (int u = 0; u < 8; ++u) {               // A tile: 128x64 f32
            int idx = tid + u * 256, rr = idx >> 4, c4 = idx & 15;
            float4 v = *(const float4*)(A + (size_t)(m0 + rr) * DD + k0 + c4 * 4);
            sts_hilo(AH, AL, rr, c4 * 8, v);
        }
        #pragma unroll
        for (int u = 0; u < 4; ++u) {               // W tile: 64x64 f32
            int idx = tid + u * 256, rr = idx >> 4, c4 = idx & 15;
            float4 v = *(const float4*)(W + (size_t)(n0 + rr) * DD + k0 + c4 * 4);
            sts_hilo(WH, WL, rr, c4 * 8, v);
        }
        __syncthreads();
        #pragma unroll
        for (int sp = 0; sp < 3; ++sp) {
            const char* Ab = (sp == 2) ? AL : AH;
            const char* Bb = (sp == 1) ? WL : WH;
            #pragma unroll
            for (int kk = 0; kk < 4; ++kk) {
                const int ko = kk * 16 + 2 * cq;
                unsigned a[2][4], b[4][2];
                #pragma unroll
                for (int mt = 0; mt < 2; ++mt) {
                    int row = wm * 32 + mt * 16 + g;
                    a[mt][0] = ldh2(Ab, row * GP + ko);
                    a[mt][1] = ldh2(Ab, (row + 8) * GP + ko);
                    a[mt][2] = ldh2(Ab, row * GP + ko + 8);
                    a[mt][3] = ldh2(Ab, (row + 8) * GP + ko + 8);
                }
                #pragma unroll
                for (int nt = 0; nt < 4; ++nt) {
                    int col = wn * 32 + nt * 8 + g;
                    b[nt][0] = ldh2(Bb, col * GP + ko);
                    b[nt][1] = ldh2(Bb, col * GP + ko + 8);
                }
                #pragma unroll
                for (int mt = 0; mt < 2; ++mt)
                    #pragma unroll
                    for (int nt = 0; nt < 4; ++nt)
                        mma_bf16(acc[mt][nt], a[mt][0], a[mt][1], a[mt][2], a[mt][3],
                                 b[nt][0], b[nt][1]);
            }
        }
        __syncthreads();
    }
    #pragma unroll
    for (int mt = 0; mt < 2; ++mt)
        #pragma unroll
        for (int nt = 0; nt < 4; ++nt) {
            int row = m0 + wm * 32 + mt * 16 + g;
            int col = n0 + wn * 32 + nt * 8 + 2 * cq;
            float b0 = bias ? bias[col] : 0.f, b1 = bias ? bias[col + 1] : 0.f;
            *(float2*)(C + (size_t)row * DD + col) =
                make_float2(acc[mt][nt][0] + b0, acc[mt][nt][1] + b1);
            *(float2*)(C + (size_t)(row + 8) * DD + col) =
                make_float2(acc[mt][nt][2] + b0, acc[mt][nt][3] + b1);
        }
}

// ===========================================================================
// Attention: CTA=(h, qtile 64, b). Flash, no-max softmax, bf16x3 mma.
// Warps 4(Mq)x2(Nk). S warp tile 16x32; O partial per warp 16x64.
// ===========================================================================
#define A_QH 0
#define A_QL 9216
#define A_KH 18432
#define A_KL 27648
#define A_VH 36864
#define A_VL 46080
#define A_LS 55296           // float[2][64]
#define A_LI 55808           // float[64]
#define A_SM 56064
#define OPITCH 68            // OSM float pitch (reuses K region)

__global__ __launch_bounds__(256) void attn_mma(
    const float* __restrict__ Q, const float* __restrict__ K,
    const float* __restrict__ V, const float* __restrict__ gprob,
    const int* __restrict__ mask, float* __restrict__ X)
{
    extern __shared__ char sm[];
    char* QH = sm + A_QH; char* QL = sm + A_QL;
    char* KH = sm + A_KH; char* KL = sm + A_KL;
    char* VH = sm + A_VH; char* VL = sm + A_VL;
    float* LSM = (float*)(sm + A_LS);
    float* LIS = (float*)(sm + A_LI);
    float* OSM = (float*)(sm + A_KH);          // reused after mainloop

    const int tid = threadIdx.x, lane = tid & 31, wid = tid >> 5;
    const int wm = wid & 3, wn = wid >> 2;
    const int g = lane >> 2, cq = lane & 3;
    const int h = blockIdx.x, qt = blockIdx.y, b = blockIdx.z;
    const int q0 = qt * 64;

    const float* Qb = Q + (size_t)b * SS * DD + h * 64;
    const float* Kb = K + (size_t)b * SS * DD + h * 64;
    const float* Vb = V + (size_t)b * SS * DD + h * 64;

    #pragma unroll
    for (int u = 0; u < 4; ++u) {               // Q tile 64x64
        int idx = tid + u * 256, rr = idx >> 4, c4 = idx & 15;
        float4 v = *(const float4*)(Qb + (size_t)(q0 + rr) * DD + c4 * 4);
        sts_hilo(QH, QL, rr, c4 * 8, v);
    }

    const int qg0 = q0 + wm * 16 + g, qg1 = qg0 + 8;
    const int*   mr0 = mask  + ((size_t)b * SS + qg0) * SS;
    const int*   mr1 = mask  + ((size_t)b * SS + qg1) * SS;
    const float* gr0 = gprob + ((size_t)b * SS + qg0) * SS;
    const float* gr1 = gprob + ((size_t)b * SS + qg1) * SS;

    float o[8][4] = {};
    float lsum0 = 0.f, lsum1 = 0.f;
    __syncthreads();

    for (int kt = 0; kt < 16; ++kt) {
        const int k0 = kt * 64;
        #pragma unroll
        for (int u = 0; u < 4; ++u) {           // K tile 64x64 [kpos][dk]
            int idx = tid + u * 256, rr = idx >> 4, c4 = idx & 15;
            float4 v = *(const float4*)(Kb + (size_t)(k0 + rr) * DD + c4 * 4);
            sts_hilo(KH, KL, rr, c4 * 8, v);
        }
        #pragma unroll
        for (int u = 0; u < 4; ++u) {           // V^T tile [d][kpos]
            int idx = tid + u * 256, kp = idx >> 4, c4 = idx & 15, d0 = c4 * 4;
            float4 v = *(const float4*)(Vb + (size_t)(k0 + kp) * DD + d0);
            split1(VH, VL, (d0 + 0) * GP + kp, v.x);
            split1(VH, VL, (d0 + 1) * GP + kp, v.y);
            split1(VH, VL, (d0 + 2) * GP + kp, v.z);
            split1(VH, VL, (d0 + 3) * GP + kp, v.w);
        }
        __syncthreads();

        // ---- S = Q.K^T (warp tile 16 x 32) ----
        float s[4][4] = {};
        #pragma unroll
        for (int sp = 0; sp < 3; ++sp) {
            const char* Ab = (sp == 2) ? QL : QH;
            const char* Bb = (sp == 1) ? KL : KH;
            #pragma unroll
            for (int kk = 0; kk < 4; ++kk) {
                const int ko = kk * 16 + 2 * cq;
                const int row = wm * 16 + g;
                unsigned a0 = ldh2(Ab, row * GP + ko);
                unsigned a1 = ldh2(Ab, (row + 8) * GP + ko);
                unsigned a2 = ldh2(Ab, row * GP + ko + 8);
                unsigned a3 = ldh2(Ab, (row + 8) * GP + ko + 8);
                #pragma unroll
                for (int nt = 0; nt < 4; ++nt) {
                    int col = wn * 32 + nt * 8 + g;
                    mma_bf16(s[nt], a0, a1, a2, a3,
                             ldh2(Bb, col * GP + ko), ldh2(Bb, col * GP + ko + 8));
                }
            }
        }

        // ---- softmax numerator (no max-sub; masked -> exact 0); pack P hi/lo ----
        unsigned PHf[4][2], PLf[4][2];
        #pragma unroll
        for (int nt = 0; nt < 4; ++nt) {
            const int kg = k0 + wn * 32 + nt * 8 + 2 * cq;
            int2   m0v = *(const int2*)(mr0 + kg);
            int2   m1v = *(const int2*)(mr1 + kg);
            float2 g0v = *(const float2*)(gr0 + kg);
            float2 g1v = *(const float2*)(gr1 + kg);
            float p00 = (m0v.x | (int)(kg     == qg0)) ? __expf(s[nt][0] * 0.125f) : 0.f;
            float p01 = (m0v.y | (int)(kg + 1 == qg0)) ? __expf(s[nt][1] * 0.125f) : 0.f;
            float p10 = (m1v.x | (int)(kg     == qg1)) ? __expf(s[nt][2] * 0.125f) : 0.f;
            float p11 = (m1v.y | (int)(kg + 1 == qg1)) ? __expf(s[nt][3] * 0.125f) : 0.f;
            lsum0 += p00 + p01;
            lsum1 += p10 + p11;
            float t00 = p00 * g0v.x, t01 = p01 * g0v.y;
            float t10 = p10 * g1v.x, t11 = p11 * g1v.y;
            unsigned h0 = pack2bf(t00, t01), h1 = pack2bf(t10, t11);
            PHf[nt][0] = h0; PHf[nt][1] = h1;
            PLf[nt][0] = pack2bf(t00 - __uint_as_float(h0 << 16),
                                 t01 - __uint_as_float(h0 & 0xFFFF0000u));
            PLf[nt][1] = pack2bf(t10 - __uint_as_float(h1 << 16),
                                 t11 - __uint_as_float(h1 & 0xFFFF0000u));
        }

        // ---- O_partial += P.V (k over this warp's 32 S-cols) ----
        #pragma unroll
        for (int sp = 0; sp < 3; ++sp) {
            const unsigned (*Pf)[2] = (sp == 2) ? PLf : PHf;
            const char* Vb_ = (sp == 1) ? VL : VH;
            #pragma unroll
            for (int kk2 = 0; kk2 < 2; ++kk2) {
                unsigned a0 = Pf[2*kk2][0], a1 = Pf[2*kk2][1];
                unsigned a2 = Pf[2*kk2+1][0], a3 = Pf[2*kk2+1][1];
                const int kl = wn * 32 + kk2 * 16 + 2 * cq;
                #pragma unroll
                for (int dn = 0; dn < 8; ++dn) {
                    int dcol = dn * 8 + g;
                    mma_bf16(o[dn], a0, a1, a2, a3,
                             ldh2(Vb_, dcol * GP + kl), ldh2(Vb_, dcol * GP + kl + 8));
                }
            }
        }
        __syncthreads();
    }

    // ---- epilogue: l reduce, O combine across wn, write out ----
    lsum0 += __shfl_xor_sync(0xFFFFFFFFu, lsum0, 1);
    lsum0 += __shfl_xor_sync(0xFFFFFFFFu, lsum0, 2);
    lsum1 += __shfl_xor_sync(0xFFFFFFFFu, lsum1, 1);
    lsum1 += __shfl_xor_sync(0xFFFFFFFFu, lsum1, 2);
    if (cq == 0) {
        LSM[wn * 64 + wm * 16 + g]     = lsum0;
        LSM[wn * 64 + wm * 16 + g + 8] = lsum1;
    }
    __syncthreads();
    if (tid < 64) LIS[tid] = 1.0f / (LSM[tid] + LSM[64 + tid]);
    if (wn == 0) {
        #pragma unroll
        for (int dn = 0; dn < 8; ++dn) {
            int r0 = wm * 16 + g, col = dn * 8 + 2 * cq;
            *(float2*)(OSM + r0 * OPITCH + col)       = make_float2(o[dn][0], o[dn][1]);
            *(float2*)(OSM + (r0 + 8) * OPITCH + col) = make_float2(o[dn][2], o[dn][3]);
        }
    }
    __syncthreads();
    if (wn == 1) {
        #pragma unroll
        for (int dn = 0; dn < 8; ++dn) {
            int r0 = wm * 16 + g, col = dn * 8 + 2 * cq;
            float2* p0 = (float2*)(OSM + r0 * OPITCH + col);
            float2* p1 = (float2*)(OSM + (r0 + 8) * OPITCH + col);
            p0->x += o[dn][0]; p0->y += o[dn][1];
            p1->x += o[dn][2]; p1->y += o[dn][3];
        }
    }
    __syncthreads();
    #pragma unroll
    for (int u = 0; u < 4; ++u) {
        int idx = tid + u * 256, rr = idx >> 4, c4 = idx & 15;
        float li = LIS[rr];
        float4 vv = *(float4*)(OSM + rr * OPITCH + c4 * 4);
        vv.x *= li; vv.y *= li; vv.z *= li; vv.w *= li;
        *(float4*)(X + ((size_t)b * SS + q0 + rr) * DD + h * 64 + c4 * 4) = vv;
    }
}

// ===========================================================================
extern "C" void kernel_launch(void* const* d_in, const int* in_sizes, int n_in,
                              void* d_out, int out_size)
{
    const float* query = (const float*)d_in[0];
    const float* key   = (const float*)d_in[1];
    const float* value = (const float*)d_in[2];
    const float* gprob = (const float*)d_in[3];
    const float* Wq    = (const float*)d_in[4];
    const float* Wk    = (const float*)d_in[5];
    const float* Wv    = (const float*)d_in[6];
    const float* Wh    = (const float*)d_in[7];
    const float* bh    = (const float*)d_in[8];
    const int*   mask  = (const int*)d_in[9];
    float* out = (float*)d_out;

    float *Qp, *Kp, *Vp, *Xp;
    cudaGetSymbolAddress((void**)&Qp, g_Q);
    cudaGetSymbolAddress((void**)&Kp, g_K);
    cudaGetSymbolAddress((void**)&Vp, g_V);
    cudaGetSymbolAddress((void**)&Xp, g_X);

    cudaFuncSetAttribute(gemm_mma, cudaFuncAttributeMaxDynamicSharedMemorySize, G_SM);
    cudaFuncSetAttribute(attn_mma, cudaFuncAttributeMaxDynamicSharedMemorySize, A_SM);

    dim3 blk(256);
    dim3 pg(DD / 64, NQ / 128);                 // (8, 64)
    gemm_mma<<<pg, blk, G_SM>>>(query, Wq, nullptr, Qp);
    gemm_mma<<<pg, blk, G_SM>>>(key,   Wk, nullptr, Kp);
    gemm_mma<<<pg, blk, G_SM>>>(value, Wv, nullptr, Vp);
    attn_mma<<<dim3(HH, SS / 64, BBB), blk, A_SM>>>(Qp, Kp, Vp, gprob, mask, Xp);
    gemm_mma<<<pg, blk, G_SM>>>(Xp, Wh, bh, out);
}

// round 7
// speedup vs baseline: 3.4778x; 1.3081x over previous
#include <cuda_runtime.h>
#include <cuda_bf16.h>

#define SS 1024
#define DD 512
#define HH 8
#define BBB 8
#define NQ (BBB*SS)
#define GP  72        // smem pitch in bf16 halves (144B rows -> conflict-free ldmatrix)
#define GPB 144

__device__ float g_Q[NQ*DD];
__device__ float g_K[NQ*DD];
__device__ float g_V[NQ*DD];
__device__ float g_X[NQ*DD];

// ---------------------------------------------------------------------------
__device__ __forceinline__ unsigned s2u(const void* p) {
    unsigned a;
    asm("{ .reg .u64 t; cvta.to.shared.u64 t, %1; cvt.u32.u64 %0, t; }" : "=r"(a) : "l"(p));
    return a;
}
__device__ __forceinline__ unsigned pack2bf(float x0, float x1) {
    unsigned r;
    asm("cvt.rn.bf16x2.f32 %0, %1, %2;" : "=r"(r) : "f"(x1), "f"(x0)); // low16=bf16(x0)
    return r;
}
__device__ __forceinline__ void mma_bf16(float c[4], unsigned a0, unsigned a1,
                                         unsigned a2, unsigned a3,
                                         unsigned b0, unsigned b1) {
    asm volatile("mma.sync.aligned.m16n8k16.row.col.f32.bf16.bf16.f32 "
        "{%0,%1,%2,%3}, {%4,%5,%6,%7}, {%8,%9}, {%0,%1,%2,%3};"
        : "+f"(c[0]), "+f"(c[1]), "+f"(c[2]), "+f"(c[3])
        : "r"(a0), "r"(a1), "r"(a2), "r"(a3), "r"(b0), "r"(b1));
}
__device__ __forceinline__ void ldm4(unsigned* r, unsigned addr) {
    asm volatile("ldmatrix.sync.aligned.m8n8.x4.shared.b16 {%0,%1,%2,%3}, [%4];"
        : "=r"(r[0]), "=r"(r[1]), "=r"(r[2]), "=r"(r[3]) : "r"(addr));
}
__device__ __forceinline__ void ldm4t(unsigned* r, unsigned addr) {
    asm volatile("ldmatrix.sync.aligned.m8n8.x4.trans.shared.b16 {%0,%1,%2,%3}, [%4];"
        : "=r"(r[0]), "=r"(r[1]), "=r"(r[2]), "=r"(r[3]) : "r"(addr));
}
// split float4 -> bf16 hi/lo, vectorized 8B stores at [r][cbyte], pitch GPB
__device__ __forceinline__ void sts_hilo(char* hib, char* lob, int r, int cbyte, float4 v) {
    unsigned hp0 = pack2bf(v.x, v.y), hp1 = pack2bf(v.z, v.w);
    float a0 = __uint_as_float(hp0 << 16), a1 = __uint_as_float(hp0 & 0xFFFF0000u);
    float a2 = __uint_as_float(hp1 << 16), a3 = __uint_as_float(hp1 & 0xFFFF0000u);
    unsigned lp0 = pack2bf(v.x - a0, v.y - a1), lp1 = pack2bf(v.z - a2, v.w - a3);
    *(uint2*)(hib + r*GPB + cbyte) = make_uint2(hp0, hp1);
    *(uint2*)(lob + r*GPB + cbyte) = make_uint2(lp0, lp1);
}

// ===========================================================================
// GEMM: C[8192,512] = A[8192,512] @ W[512,512]^T (+bias)
// CTA 128x64, 8 warps 4(M)x2(N), warp tile 32x32, k-chunks of 64, ldmatrix.
// ===========================================================================
#define G_AH 0
#define G_AL 18432
#define G_WH 36864
#define G_WL 46080
#define G_SM 55296

__global__ __launch_bounds__(256) void gemm_mma(
    const float* __restrict__ A, const float* __restrict__ W,
    const float* __restrict__ bias, float* __restrict__ C)
{
    extern __shared__ char sm[];
    char* AH = sm + G_AH; char* AL = sm + G_AL;
    char* WH = sm + G_WH; char* WL = sm + G_WL;
    const unsigned sb = s2u(sm);
    const int tid = threadIdx.x, lane = tid & 31, wid = tid >> 5;
    const int wm = wid & 3, wn = wid >> 2;
    const int g = lane >> 2, cq = lane & 3;
    const int m0 = blockIdx.y * 128, n0 = blockIdx.x * 64;

    // ldmatrix per-lane address parts
    const int aRow = lane & 15, aCol = (lane >> 4) << 3;                 // A-style (and V-trans)
    const int bRow = (lane & 7) + ((lane >> 4) << 3), bCol = ((lane >> 3) & 1) << 3; // B-style
    const unsigned aH0 = sb + G_AH + ((wm*32 + aRow)*GP + aCol)*2, aH1 = aH0 + 16*GPB;
    const unsigned aL0 = sb + G_AL + ((wm*32 + aRow)*GP + aCol)*2, aL1 = aL0 + 16*GPB;
    const unsigned wH0 = sb + G_WH + ((wn*32 + bRow)*GP + bCol)*2, wH1 = wH0 + 16*GPB;
    const unsigned wL0 = sb + G_WL + ((wn*32 + bRow)*GP + bCol)*2, wL1 = wL0 + 16*GPB;

    float acc[2][4][4] = {};

    for (int kc = 0; kc < 8; ++kc) {
        const int k0 = kc * 64;
        #pragma unroll
        for (int u = 0; u < 8; ++u) {               // A tile 128x64
            int idx = tid + u * 256, rr = idx >> 4, c4 = idx & 15;
            float4 v = *(const float4*)(A + (size_t)(m0 + rr) * DD + k0 + c4 * 4);
            sts_hilo(AH, AL, rr, c4 * 8, v);
        }
        #pragma unroll
        for (int u = 0; u < 4; ++u) {               // W tile 64x64
            int idx = tid + u * 256, rr = idx >> 4, c4 = idx & 15;
            float4 v = *(const float4*)(W + (size_t)(n0 + rr) * DD + k0 + c4 * 4);
            sts_hilo(WH, WL, rr, c4 * 8, v);
        }
        __syncthreads();
        #pragma unroll
        for (int kk = 0; kk < 4; ++kk) {
            const unsigned ko2 = kk * 32;
            unsigned ah[8], al[8], bh[8], bl[8];
            ldm4(ah,     aH0 + ko2); ldm4(ah + 4, aH1 + ko2);
            ldm4(al,     aL0 + ko2); ldm4(al + 4, aL1 + ko2);
            ldm4(bh,     wH0 + ko2); ldm4(bh + 4, wH1 + ko2);
            ldm4(bl,     wL0 + ko2); ldm4(bl + 4, wL1 + ko2);
            #pragma unroll
            for (int mt = 0; mt < 2; ++mt) {
                unsigned* ap = ah + mt * 4;
                unsigned* lp = al + mt * 4;
                #pragma unroll
                for (int nt = 0; nt < 4; ++nt) {
                    mma_bf16(acc[mt][nt], ap[0], ap[1], ap[2], ap[3], bh[2*nt], bh[2*nt+1]);
                    mma_bf16(acc[mt][nt], ap[0], ap[1], ap[2], ap[3], bl[2*nt], bl[2*nt+1]);
                    mma_bf16(acc[mt][nt], lp[0], lp[1], lp[2], lp[3], bh[2*nt], bh[2*nt+1]);
                }
            }
        }
        __syncthreads();
    }
    #pragma unroll
    for (int mt = 0; mt < 2; ++mt)
        #pragma unroll
        for (int nt = 0; nt < 4; ++nt) {
            int row = m0 + wm * 32 + mt * 16 + g;
            int col = n0 + wn * 32 + nt * 8 + 2 * cq;
            float b0 = bias ? bias[col] : 0.f, b1 = bias ? bias[col + 1] : 0.f;
            *(float2*)(C + (size_t)row * DD + col) =
                make_float2(acc[mt][nt][0] + b0, acc[mt][nt][1] + b1);
            *(float2*)(C + (size_t)(row + 8) * DD + col) =
                make_float2(acc[mt][nt][2] + b0, acc[mt][nt][3] + b1);
        }
}

// ===========================================================================
// Attention: CTA=(h, qtile 64, b). Flash, no-max softmax, bf16x3.
// V kept NATURAL [k][d] in smem; P.V B-frags via ldmatrix.trans.
// ===========================================================================
#define A_QH 0
#define A_QL 9216
#define A_KH 18432
#define A_KL 27648
#define A_VH 36864
#define A_VL 46080
#define A_LS 55296
#define A_LI 55808
#define A_SM 56064
#define OPITCH 68

__global__ __launch_bounds__(256) void attn_mma(
    const float* __restrict__ Q, const float* __restrict__ K,
    const float* __restrict__ V, const float* __restrict__ gprob,
    const int* __restrict__ mask, float* __restrict__ X)
{
    extern __shared__ char sm[];
    char* QH = sm + A_QH; char* QL = sm + A_QL;
    char* KH = sm + A_KH; char* KL = sm + A_KL;
    char* VH = sm + A_VH; char* VL = sm + A_VL;
    float* LSM = (float*)(sm + A_LS);
    float* LIS = (float*)(sm + A_LI);
    float* OSM = (float*)(sm + A_KH);          // reused after mainloop
    const unsigned sb = s2u(sm);

    const int tid = threadIdx.x, lane = tid & 31, wid = tid >> 5;
    const int wm = wid & 3, wn = wid >> 2;
    const int g = lane >> 2, cq = lane & 3;
    const int h = blockIdx.x, qt = blockIdx.y, b = blockIdx.z;
    const int q0 = qt * 64;

    const int aRow = lane & 15, aCol = (lane >> 4) << 3;
    const int bRow = (lane & 7) + ((lane >> 4) << 3), bCol = ((lane >> 3) & 1) << 3;
    const unsigned qHa = sb + A_QH + ((wm*16 + aRow)*GP + aCol)*2;
    const unsigned qLa = qHa + (A_QL - A_QH);
    const unsigned kH0 = sb + A_KH + ((wn*32 + bRow)*GP + bCol)*2, kH1 = kH0 + 16*GPB;
    const unsigned kL0 = kH0 + (A_KL - A_KH),                      kL1 = kL0 + 16*GPB;
    const unsigned vHa = sb + A_VH + ((wn*32 + aRow)*GP + aCol)*2; // rows = k
    const unsigned vLa = vHa + (A_VL - A_VH);

    const float* Qb = Q + (size_t)b * SS * DD + h * 64;
    const float* Kb = K + (size_t)b * SS * DD + h * 64;
    const float* Vb = V + (size_t)b * SS * DD + h * 64;

    #pragma unroll
    for (int u = 0; u < 4; ++u) {               // Q tile 64x64
        int idx = tid + u * 256, rr = idx >> 4, c4 = idx & 15;
        float4 v = *(const float4*)(Qb + (size_t)(q0 + rr) * DD + c4 * 4);
        sts_hilo(QH, QL, rr, c4 * 8, v);
    }

    const int qg0 = q0 + wm * 16 + g, qg1 = qg0 + 8;
    const int*   mr0 = mask  + ((size_t)b * SS + qg0) * SS;
    const int*   mr1 = mask  + ((size_t)b * SS + qg1) * SS;
    const float* gr0 = gprob + ((size_t)b * SS + qg0) * SS;
    const float* gr1 = gprob + ((size_t)b * SS + qg1) * SS;

    float o[8][4] = {};
    float lsum0 = 0.f, lsum1 = 0.f;
    __syncthreads();

    for (int kt = 0; kt < 16; ++kt) {
        const int k0 = kt * 64;
        #pragma unroll
        for (int u = 0; u < 4; ++u) {           // K tile 64x64 [kpos][dk]
            int idx = tid + u * 256, rr = idx >> 4, c4 = idx & 15;
            float4 v = *(const float4*)(Kb + (size_t)(k0 + rr) * DD + c4 * 4);
            sts_hilo(KH, KL, rr, c4 * 8, v);
        }
        #pragma unroll
        for (int u = 0; u < 4; ++u) {           // V tile 64x64 NATURAL [kpos][d]
            int idx = tid + u * 256, rr = idx >> 4, c4 = idx & 15;
            float4 v = *(const float4*)(Vb + (size_t)(k0 + rr) * DD + c4 * 4);
            sts_hilo(VH, VL, rr, c4 * 8, v);
        }
        __syncthreads();

        // ---- S = Q.K^T (warp tile 16x32), dedup frag loads across splits ----
        float s[4][4] = {};
        #pragma unroll
        for (int kk = 0; kk < 4; ++kk) {
            const unsigned ko2 = kk * 32;
            unsigned aH[4], aL[4], bh[8], bl[8];
            ldm4(aH, qHa + ko2);
            ldm4(aL, qLa + ko2);
            ldm4(bh,     kH0 + ko2); ldm4(bh + 4, kH1 + ko2);
            ldm4(bl,     kL0 + ko2); ldm4(bl + 4, kL1 + ko2);
            #pragma unroll
            for (int nt = 0; nt < 4; ++nt) {
                mma_bf16(s[nt], aH[0], aH[1], aH[2], aH[3], bh[2*nt], bh[2*nt+1]);
                mma_bf16(s[nt], aH[0], aH[1], aH[2], aH[3], bl[2*nt], bl[2*nt+1]);
                mma_bf16(s[nt], aL[0], aL[1], aL[2], aL[3], bh[2*nt], bh[2*nt+1]);
            }
        }

        // ---- softmax numerator (no max-sub; masked -> exact 0); pack P hi/lo ----
        unsigned PHf[4][2], PLf[4][2];
        #pragma unroll
        for (int nt = 0; nt < 4; ++nt) {
            const int kg = k0 + wn * 32 + nt * 8 + 2 * cq;
            int2   m0v = *(const int2*)(mr0 + kg);
            int2   m1v = *(const int2*)(mr1 + kg);
            float2 g0v = *(const float2*)(gr0 + kg);
            float2 g1v = *(const float2*)(gr1 + kg);
            float p00 = (m0v.x | (int)(kg     == qg0)) ? __expf(s[nt][0] * 0.125f) : 0.f;
            float p01 = (m0v.y | (int)(kg + 1 == qg0)) ? __expf(s[nt][1] * 0.125f) : 0.f;
            float p10 = (m1v.x | (int)(kg     == qg1)) ? __expf(s[nt][2] * 0.125f) : 0.f;
            float p11 = (m1v.y | (int)(kg + 1 == qg1)) ? __expf(s[nt][3] * 0.125f) : 0.f;
            lsum0 += p00 + p01;
            lsum1 += p10 + p11;
            float t00 = p00 * g0v.x, t01 = p01 * g0v.y;
            float t10 = p10 * g1v.x, t11 = p11 * g1v.y;
            unsigned h0 = pack2bf(t00, t01), h1 = pack2bf(t10, t11);
            PHf[nt][0] = h0; PHf[nt][1] = h1;
            PLf[nt][0] = pack2bf(t00 - __uint_as_float(h0 << 16),
                                 t01 - __uint_as_float(h0 & 0xFFFF0000u));
            PLf[nt][1] = pack2bf(t10 - __uint_as_float(h1 << 16),
                                 t11 - __uint_as_float(h1 & 0xFFFF0000u));
        }

        // ---- O_partial += P.V ; V B-frags via ldmatrix.trans, dedup splits ----
        #pragma unroll
        for (int kk2 = 0; kk2 < 2; ++kk2) {
            const unsigned kofs = (unsigned)kk2 * 16 * GPB;
            unsigned vh[16], vl[16];
            #pragma unroll
            for (int dq = 0; dq < 4; ++dq) {
                ldm4t(vh + dq * 4, vHa + kofs + dq * 32);
                ldm4t(vl + dq * 4, vLa + kofs + dq * 32);
            }
            unsigned ph0 = PHf[2*kk2][0], ph1 = PHf[2*kk2][1];
            unsigned ph2 = PHf[2*kk2+1][0], ph3 = PHf[2*kk2+1][1];
            unsigned pl0 = PLf[2*kk2][0], pl1 = PLf[2*kk2][1];
            unsigned pl2 = PLf[2*kk2+1][0], pl3 = PLf[2*kk2+1][1];
            #pragma unroll
            for (int dn = 0; dn < 8; ++dn) {
                mma_bf16(o[dn], ph0, ph1, ph2, ph3, vh[2*dn], vh[2*dn+1]);
                mma_bf16(o[dn], ph0, ph1, ph2, ph3, vl[2*dn], vl[2*dn+1]);
                mma_bf16(o[dn], pl0, pl1, pl2, pl3, vh[2*dn], vh[2*dn+1]);
            }
        }
        __syncthreads();
    }

    // ---- epilogue: l reduce, O combine across wn, write out ----
    lsum0 += __shfl_xor_sync(0xFFFFFFFFu, lsum0, 1);
    lsum0 += __shfl_xor_sync(0xFFFFFFFFu, lsum0, 2);
    lsum1 += __shfl_xor_sync(0xFFFFFFFFu, lsum1, 1);
    lsum1 += __shfl_xor_sync(0xFFFFFFFFu, lsum1, 2);
    if (cq == 0) {
        LSM[wn * 64 + wm * 16 + g]     = lsum0;
        LSM[wn * 64 + wm * 16 + g + 8] = lsum1;
    }
    __syncthreads();
    if (tid < 64) LIS[tid] = 1.0f / (LSM[tid] + LSM[64 + tid]);
    if (wn == 0) {
        #pragma unroll
        for (int dn = 0; dn < 8; ++dn) {
            int r0 = wm * 16 + g, col = dn * 8 + 2 * cq;
            *(float2*)(OSM + r0 * OPITCH + col)       = make_float2(o[dn][0], o[dn][1]);
            *(float2*)(OSM + (r0 + 8) * OPITCH + col) = make_float2(o[dn][2], o[dn][3]);
        }
    }
    __syncthreads();
    if (wn == 1) {
        #pragma unroll
        for (int dn = 0; dn < 8; ++dn) {
            int r0 = wm * 16 + g, col = dn * 8 + 2 * cq;
            float2* p0 = (float2*)(OSM + r0 * OPITCH + col);
            float2* p1 = (float2*)(OSM + (r0 + 8) * OPITCH + col);
            p0->x += o[dn][0]; p0->y += o[dn][1];
            p1->x += o[dn][2]; p1->y += o[dn][3];
        }
    }
    __syncthreads();
    #pragma unroll
    for (int u = 0; u < 4; ++u) {
        int idx = tid + u * 256, rr = idx >> 4, c4 = idx & 15;
        float li = LIS[rr];
        float4 vv = *(float4*)(OSM + rr * OPITCH + c4 * 4);
        vv.x *= li; vv.y *= li; vv.z *= li; vv.w *= li;
        *(float4*)(X + ((size_t)b * SS + q0 + rr) * DD + h * 64 + c4 * 4) = vv;
    }
}

// ===========================================================================
extern "C" void kernel_launch(void* const* d_in, const int* in_sizes, int n_in,
                              void* d_out, int out_size)
{
    const float* query = (const float*)d_in[0];
    const float* key   = (const float*)d_in[1];
    const float* value = (const float*)d_in[2];
    const float* gprob = (const float*)d_in[3];
    const float* Wq    = (const float*)d_in[4];
    const float* Wk    = (const float*)d_in[5];
    const float* Wv    = (const float*)d_in[6];
    const float* Wh    = (const float*)d_in[7];
    const float* bh    = (const float*)d_in[8];
    const int*   mask  = (const int*)d_in[9];
    float* out = (float*)d_out;

    float *Qp, *Kp, *Vp, *Xp;
    cudaGetSymbolAddress((void**)&Qp, g_Q);
    cudaGetSymbolAddress((void**)&Kp, g_K);
    cudaGetSymbolAddress((void**)&Vp, g_V);
    cudaGetSymbolAddress((void**)&Xp, g_X);

    cudaFuncSetAttribute(gemm_mma, cudaFuncAttributeMaxDynamicSharedMemorySize, G_SM);
    cudaFuncSetAttribute(attn_mma, cudaFuncAttributeMaxDynamicSharedMemorySize, A_SM);

    dim3 blk(256);
    dim3 pg(DD / 64, NQ / 128);                 // (8, 64)
    gemm_mma<<<pg, blk, G_SM>>>(query, Wq, nullptr, Qp);
    gemm_mma<<<pg, blk, G_SM>>>(key,   Wk, nullptr, Kp);
    gemm_mma<<<pg, blk, G_SM>>>(value, Wv, nullptr, Vp);
    attn_mma<<<dim3(HH, SS / 64, BBB), blk, A_SM>>>(Qp, Kp, Vp, gprob, mask, Xp);
    gemm_mma<<<pg, blk, G_SM>>>(Xp, Wh, bh, out);
}